// round 8
// baseline (speedup 1.0000x reference)
#include <cuda_runtime.h>
#include <math.h>

#define TLEN 512
#define NBATCH 32
#define BIGV 1e8f
#define DRING 32

// Per-batch partials: [0..31]=sum_sq, [32..63]=sum_abs, [64..95]=pcc_b, [96..127]=|dtw_b|
__device__ float g_part[4 * NBATCH];
__device__ unsigned int g_tick;   // zero-initialized at load; reset by winner each call

__device__ __forceinline__ float ex2(float x) {
    float r; asm("ex2.approx.f32 %0, %1;" : "=f"(r) : "f"(x)); return r;
}
__device__ __forceinline__ float lg2(float x) {
    float r; asm("lg2.approx.f32 %0, %1;" : "=f"(r) : "f"(x)); return r;
}

// softmin, gamma=0.1:  m - 0.1*ln(1 + e^{10(m-mid)} + e^{10(m-M)})
// exp/log constants folded into raw ex2/lg2: 10/ln2, 0.1*ln2.
__device__ __forceinline__ float softmin3(float a, float b, float c) {
    float lo = fminf(a, b), hi = fmaxf(a, b);
    float m   = fminf(lo, c);
    float mid = fminf(hi, fmaxf(lo, c));
    float M   = fmaxf(hi, c);
    float s = 1.0f + ex2((m - mid) * 14.4269504088896f) + ex2((m - M) * 14.4269504088896f);
    return m - 0.0693147180559945f * lg2(s);
}

__device__ __forceinline__ float block_sum(float v, float* red) {
    const unsigned full = 0xffffffffu;
#pragma unroll
    for (int o = 16; o > 0; o >>= 1) v += __shfl_down_sync(full, v, o);
    int lane = threadIdx.x & 31;
    int w = threadIdx.x >> 5;
    if (lane == 0) red[w] = v;
    __syncthreads();
    if (w == 0) {
        float t = (lane < 16) ? red[lane] : 0.0f;
#pragma unroll
        for (int o = 8; o > 0; o >>= 1) t += __shfl_down_sync(full, t, o);
        if (lane == 0) red[0] = t;
    }
    __syncthreads();
    float r = red[0];
    __syncthreads();
    return r;
}

__global__ __launch_bounds__(TLEN, 1)
void seqloss_main(const float* __restrict__ pred_map,
                  const int* __restrict__ lat_idx,
                  const float* __restrict__ omega,
                  const float* __restrict__ omni_ts,
                  float* __restrict__ out)
{
    const int b = blockIdx.x;
    const int tid = threadIdx.x;
    const int lane = tid & 31;
    const int w = tid >> 5;
    const unsigned full = 0xffffffffu;

    __shared__ float sv[2][TLEN];     // HUX double buffer
    __shared__ float ysh[TLEN];       // v_out_scaled (random access by j)
    __shared__ float red[16];
    __shared__ volatile unsigned long long hand[16][DRING];  // per-warp boundary ring {tag|val}
    __shared__ volatile int prog[17];                        // per-warp progress (throttle)
    __shared__ int swin;

    // C = dr*omega/dphi ; dr = (215-21.5)*695700/200 = 673089.75 ; dphi = 2pi/512
    const float K = (float)(673089.75 * 512.0 / 6.283185307179586476925287);
    const float C = K * omega[b];

    // ---- gather v_in ----
    const int base = b * TLEN + tid;
    const int lat = lat_idx[base];
    float v = pred_map[base * 128 + lat];

    // ---- HUX: 200 upwind steps, 1 step per barrier (proven R6 form) ----
    sv[0][tid] = v;
    __syncthreads();
    int cur = 0;
    for (int k = 0; k < 200; ++k) {
        float vr = sv[cur][(tid + 1) & (TLEN - 1)];
        v += __fdividef(C * (vr - v), fmaxf(v, 1.0f));
        sv[cur ^ 1][tid] = v;
        cur ^= 1;
        __syncthreads();
    }

    out[base] = v;

    const float vs = (v - 200.0f) / 1000.0f;
    const float xi = (omni_ts[base] - 200.0f) / 1000.0f;   // omni_scaled, own row
    ysh[tid] = vs;
    __syncthreads();

    // ---- per-batch reductions ----
    const float diff = vs - xi;
    const float s_sq = block_sum(diff * diff, red);
    const float s_ab = block_sum(fabsf(diff), red);
    const float s_v  = block_sum(vs, red);
    const float s_o  = block_sum(xi, red);
    const float vmean = s_v * (1.0f / TLEN);
    const float omean = s_o * (1.0f / TLEN);
    const float pc = vs - vmean;
    const float tc = xi - omean;
    const float s_nt = block_sum(pc * tc, red);
    const float s_p2 = block_sum(pc * pc, red);
    const float s_t2 = block_sum(tc * tc, red);
    const float pcc_b = s_nt / (sqrtf(s_p2) * sqrtf(s_t2));

    // ---- soft-DTW: barrier-free shfl wavefront + per-warp ring handoff ----
    // Thread i = row i. At step p it computes R(i, p-i) from:
    //   up   = R(i-1, p-1-(i-1)) : neighbor's value from last step (shfl_up / ring)
    //   left = R(i, p-1-i)       : own previous value (register)
    //   diag = R(i-1, p-2-(i-1)) : neighbor's value from two steps ago (kept register)
    ((volatile unsigned long long*)hand)[tid] = 0xFFFFFFFF00000000ULL;  // 512 = 16*32 slots
    if (tid < 16) prog[tid] = 32 * tid - 1;
    if (tid == 16) prog[16] = 0x3fffffff;
    __syncthreads();

    float rn_prev = BIGV;
    if (tid == 0) {
        float d0 = xi - vs;          // row 0: (os0 - vs0)^2 = R(0,0)
        rn_prev = d0 * d0;
    }
    float dgv = BIGV;                // R(i-1, j-1) carried forward
    const int wbase = 32 * w;
    const int pstart = (w == 0) ? 1 : wbase;
    const int pend = wbase + 542;    // last step where lane 31 (row wbase+31) is active

    for (int p = pstart; p <= pend; ++p) {
        // producer throttle: don't run >30 tags ahead of consumer warp (ring=32)
        if (w < 15) { while (p - prog[w + 1] >= 30) {} }
        // neighbor value for this step
        float nb = __shfl_up_sync(full, rn_prev, 1);
        const bool need = (w > 0) && (p <= wbase + 511);   // lane0 row active window
        if (need) {
            const unsigned want = (unsigned)(p - 1);
            unsigned long long u;
            do { u = hand[w - 1][(p - 1) & (DRING - 1)]; } while ((unsigned)(u >> 32) != want);
            if (lane == 0) nb = __uint_as_float((unsigned)u);
        } else if (lane == 0) {
            nb = BIGV;               // row -1 / inactive boundary
        }
        const int j = p - tid;
        float rn = BIGV;
        if (j >= 0 && j < TLEN) {
            float dy = xi - ysh[j];
            rn = dy * dy + softmin3(nb, rn_prev, dgv);
        }
        dgv = nb;                    // becomes diag for next step
        rn_prev = rn;
        if (w < 15 && lane == 31)
            hand[w][p & (DRING - 1)] =
                ((unsigned long long)(unsigned)p << 32) | (unsigned long long)__float_as_uint(rn);
        if (lane == 0) prog[w] = p;
    }
    // thread 511 now holds R(T-1, T-1) in rn_prev (p = 1022 was its last step)

    if (tid == TLEN - 1) {
        g_part[b]              = s_sq;
        g_part[NBATCH + b]     = s_ab;
        g_part[2 * NBATCH + b] = pcc_b;
        g_part[3 * NBATCH + b] = fabsf(rn_prev);
        __threadfence();
        unsigned t = atomicAdd(&g_tick, 1);
        swin = (t == NBATCH - 1) ? 1 : 0;
    }
    __syncthreads();

    // winner block folds the 4x32 partials into the 4 scalar losses
    if (swin) {
        if (tid < 32) {
            float sq  = g_part[tid];
            float ab  = g_part[NBATCH + tid];
            float pcc = g_part[2 * NBATCH + tid];
            float dtw = g_part[3 * NBATCH + tid];
#pragma unroll
            for (int o = 16; o > 0; o >>= 1) {
                sq  += __shfl_down_sync(full, sq, o);
                ab  += __shfl_down_sync(full, ab, o);
                pcc += __shfl_down_sync(full, pcc, o);
                dtw += __shfl_down_sync(full, dtw, o);
            }
            if (tid == 0) {
                out[NBATCH * TLEN + 0] = ab;                           // mae_loss
                out[NBATCH * TLEN + 1] = 1.0f - pcc * (1.0f / 32.0f);  // pcc_loss
                out[NBATCH * TLEN + 2] = dtw * (1.0f / 32.0f);         // dtw_loss
                out[NBATCH * TLEN + 3] = sqrtf(sq);                    // rmse_loss
            }
        }
        if (tid == 64) g_tick = 0;   // re-arm for next graph replay
    }
}

extern "C" void kernel_launch(void* const* d_in, const int* in_sizes, int n_in,
                              void* d_out, int out_size) {
    const float* pred_map = (const float*)d_in[0];
    const int*   lat_idx  = (const int*)d_in[1];
    const float* omega    = (const float*)d_in[2];
    const float* omni_ts  = (const float*)d_in[3];
    float* out = (float*)d_out;

    seqloss_main<<<NBATCH, TLEN>>>(pred_map, lat_idx, omega, omni_ts, out);
}